// round 1
// baseline (speedup 1.0000x reference)
#include <cuda_runtime.h>
#include <cstdint>
#include <cstddef>

// ---------------- problem constants ----------------
#define SS 50
#define UU 128
#define NN 20002
#define HH 256
#define UCNT 5000
#define NNZG 200000
#define NNZI 100000
#define MM (SS*UU)          // 6400
#define NP 20096            // 20002 padded up to multiple of 128 (157*128)

// ---------------- device scratch (no allocs allowed) ----------------
__device__ float g_ew   [(size_t)NN*HH];     // encoder_weight (segment_sum)
__device__ float g_ewu  [(size_t)UCNT*HH];   // ew_user
__device__ float g_upref[(size_t)UU*HH];     // user_pref gathered
__device__ float g_pug  [(size_t)UU*HH];     // p_u gathered
__device__ float g_xemb [(size_t)MM*HH];
__device__ float g_sim  [MM];
__device__ float g_q    [(size_t)MM*HH];
__device__ float g_k    [(size_t)MM*HH];
__device__ float g_v    [(size_t)MM*HH];
__device__ float g_av   [(size_t)MM*HH];
__device__ float g_t1   [(size_t)MM*HH];
__device__ float g_h1   [(size_t)MM*HH];
__device__ float g_f1   [(size_t)MM*4*HH];
__device__ float g_t2   [(size_t)MM*HH];
__device__ float g_h2   [(size_t)MM*HH];
__device__ float g_outw [(size_t)MM*HH];
__device__ float g_Ag   [(size_t)MM*HH];     // gathered out_w rows (by indexs)
__device__ float g_Bp   [(size_t)512*NP];    // fc_w padded (512 x 20096)
__device__ float g_fcbp [NP];                // fc_b padded
__device__ float g_PU   [(size_t)UU*NP];     // p_u @ fc_w[256:] + fc_b
__device__ unsigned char g_need [NN];
__device__ unsigned char g_umask[UCNT];

// ---------------- zero accumulators + masks ----------------
__global__ void k_zero()
{
    int i = blockIdx.x * blockDim.x + threadIdx.x;
    int stride = gridDim.x * blockDim.x;
    const int tot = NN*HH + UCNT*HH;
    for (int j = i; j < tot; j += stride) {
        if (j < NN*HH) g_ew[j] = 0.f; else g_ewu[j - NN*HH] = 0.f;
    }
    if (i < NN)   g_need[i]  = 0;
    if (i < UCNT) g_umask[i] = 0;
}

__global__ void k_setmask(const int* __restrict__ x, const int* __restrict__ au)
{
    int i = blockIdx.x * blockDim.x + threadIdx.x;
    if (i < MM) { int xv = x[i]; if (xv < NN-2) g_need[xv] = 1; }
    if (i < UU) g_umask[au[i]] = 1;
}

// ---------------- repack fc_w into padded B ----------------
__global__ void k_repack(const float* __restrict__ fcw, const float* __restrict__ fcb)
{
    int i = blockIdx.x * blockDim.x + threadIdx.x;
    int stride = gridDim.x * blockDim.x;
    const int tot = 512 * NP;
    for (int j = i; j < tot; j += stride) {
        int k = j / NP, n = j - k * NP;
        g_Bp[j] = (n < NN) ? fcw[(size_t)k * NN + n] : 0.f;
    }
    if (i < NP) g_fcbp[i] = (i < NN) ? fcb[i] : 0.f;
}

// ---------------- masked sparse scatter (warp per edge) ----------------
__global__ void k_scatter(const int* __restrict__ rows, const int* __restrict__ cols,
                          const float* __restrict__ vals, const float* __restrict__ enc,
                          int nnz, int which)
{
    int e = (blockIdx.x * blockDim.x + threadIdx.x) >> 5;
    if (e >= nnz) return;
    int lane = threadIdx.x & 31;
    int r = rows[e];
    const unsigned char* mask = which ? g_umask : g_need;
    if (!mask[r]) return;
    float v = vals[e];
    float* dst = (which ? g_ewu : g_ew) + (size_t)r * HH;
    const float4* src = (const float4*)(enc + (size_t)cols[e] * HH);
#pragma unroll
    for (int j = 0; j < 2; j++) {
        float4 t = src[lane + 32*j];
        int h = (lane + 32*j) * 4;
        atomicAdd(dst + h + 0, v * t.x);
        atomicAdd(dst + h + 1, v * t.y);
        atomicAdd(dst + h + 2, v * t.z);
        atomicAdd(dst + h + 3, v * t.w);
    }
}

// ---------------- small gathers ----------------
__global__ void k_upref(const int* __restrict__ au)
{
    int u = blockIdx.x, h = threadIdx.x;
    g_upref[(size_t)u*HH + h] = g_ewu[(size_t)au[u]*HH + h];
}
__global__ void k_pug(const int* __restrict__ au, const float* __restrict__ ut)
{
    int u = blockIdx.x, h = threadIdx.x;
    g_pug[(size_t)u*HH + h] = ut[(size_t)au[u]*HH + h];
}

// ---------------- x_emb gather + sim ----------------
__global__ void k_xemb(const int* __restrict__ x, const float* __restrict__ enc)
{
    int m = blockIdx.x, h = threadIdx.x;
    int u = m & (UU-1);
    int xv = x[m];
    float val = (xv >= NN-2) ? enc[(size_t)xv*HH + h] : g_ew[(size_t)xv*HH + h];
    g_xemb[(size_t)m*HH + h] = val;
    float d = g_upref[(size_t)u*HH + h] - val;
    __shared__ float red[HH];
    red[h] = d * d;
    __syncthreads();
    for (int s2 = 128; s2 > 0; s2 >>= 1) {
        if (h < s2) red[h] += red[h + s2];
        __syncthreads();
    }
    if (h == 0) g_sim[m] = expf(-sqrtf(red[0]));
}

// ---------------- causal attention (block per u) ----------------
__global__ void k_attn()
{
    int u = blockIdx.x;
    int warp = threadIdx.x >> 5, lane = threadIdx.x & 31;
    __shared__ float sp[8][56];
    for (int i = warp; i < SS; i += 8) {
        const float* qi = g_q + ((size_t)i*UU + u) * HH;
        float mx = -1e30f;
        for (int j = 0; j <= i; j++) {
            const float* kj = g_k + ((size_t)j*UU + u) * HH;
            float d = 0.f;
#pragma unroll
            for (int t = 0; t < 8; t++) d += qi[lane + 32*t] * kj[lane + 32*t];
            for (int o = 16; o; o >>= 1) d += __shfl_xor_sync(0xffffffffu, d, o);
            d *= 0.0625f;                       // 1/sqrt(256)
            sp[warp][j] = d;                    // all lanes write same value
            mx = fmaxf(mx, d);
        }
        __syncwarp();
        float ssum = 0.f;
        for (int j = lane; j <= i; j += 32) {
            float e = expf(sp[warp][j] - mx);
            sp[warp][j] = e;
            ssum += e;
        }
        __syncwarp();
        for (int o = 16; o; o >>= 1) ssum += __shfl_xor_sync(0xffffffffu, ssum, o);
        float inv = 1.f / ssum;
        float acc[8];
#pragma unroll
        for (int t = 0; t < 8; t++) acc[t] = 0.f;
        for (int j = 0; j <= i; j++) {
            float p = sp[warp][j] * inv;
            const float* vj = g_v + ((size_t)j*UU + u) * HH;
#pragma unroll
            for (int t = 0; t < 8; t++) acc[t] = fmaf(p, vj[lane + 32*t], acc[t]);
        }
        float* o = g_av + ((size_t)i*UU + u) * HH;
#pragma unroll
        for (int t = 0; t < 8; t++) o[lane + 32*t] = acc[t];
        __syncwarp();
    }
}

// ---------------- residual + LayerNorm ----------------
__global__ void k_ln(const float* __restrict__ Xres, const float* __restrict__ Y,
                     float* __restrict__ Out, const float* __restrict__ g,
                     const float* __restrict__ b)
{
    int m = blockIdx.x, h = threadIdx.x;
    float v = Xres[(size_t)m*HH + h] + Y[(size_t)m*HH + h];
    __shared__ float red[HH];
    red[h] = v;
    __syncthreads();
    for (int s2 = 128; s2 > 0; s2 >>= 1) { if (h < s2) red[h] += red[h + s2]; __syncthreads(); }
    float mu = red[0] * (1.f / HH);
    __syncthreads();
    float d = v - mu;
    red[h] = d * d;
    __syncthreads();
    for (int s2 = 128; s2 > 0; s2 >>= 1) { if (h < s2) red[h] += red[h + s2]; __syncthreads(); }
    float var = red[0] * (1.f / HH);
    Out[(size_t)m*HH + h] = d * rsqrtf(var + 1e-5f) * g[h] + b[h];
}

// ---------------- spatial weighting (block per (i,u)) ----------------
__global__ void k_spatial(const float* __restrict__ s)
{
    int m = blockIdx.x;
    int i = m >> 7, u = m & (UU-1);
    int h = threadIdx.x;
    __shared__ float w[64];
    __shared__ float sumw;
    float sx = s[((size_t)i*UU + u)*2 + 0];
    float sy = s[((size_t)i*UU + u)*2 + 1];
    if (h < SS) {
        float wj = 0.f;
        if (h <= i) {
            float dx = sx - s[((size_t)h*UU + u)*2 + 0];
            float dy = sy - s[((size_t)h*UU + u)*2 + 1];
            wj = (expf(-sqrtf(dx*dx + dy*dy)) + 1e-10f) * g_sim[(size_t)h*UU + u];
        }
        w[h] = wj;
    }
    __syncthreads();
    if (h == 0) {
        float t = 0.f;
        for (int j = 0; j < SS; j++) t += w[j];
        sumw = t;
    }
    __syncthreads();
    float acc = 0.f;
    for (int j = 0; j <= i; j++)
        acc = fmaf(w[j], g_h2[((size_t)j*UU + u)*HH + h], acc);
    g_outw[(size_t)m*HH + h] = acc / sumw;
}

// ---------------- gather out_w rows by indexs ----------------
__global__ void k_buildA(const int* __restrict__ indexs)
{
    int m = blockIdx.x, h = threadIdx.x;
    int u = m & (UU-1);
    int j = indexs[m];
    g_Ag[(size_t)m*HH + h] = g_outw[((size_t)j*UU + u)*HH + h];
}

// ---------------- generic fp32 SGEMM (128x128x16, 8x8 per thread) ----------------
// C[M x ldb] = A[M x K] @ B[K x ldb]  (+bias, +relu)        when PU == nullptr
// out[M x 20002] = A@B + PU[m%128, :] (bounded store)        when PU != nullptr
__global__ void __launch_bounds__(256, 2)
sgemm_k(const float* __restrict__ A, const float* __restrict__ B,
        float* __restrict__ C, int K, int ldb,
        const float* __restrict__ bias, int relu,
        const float* __restrict__ PU)
{
    __shared__ float As[16][132];
    __shared__ float Bs[16][128];
    int tid = threadIdx.x;
    int tx = tid & 15, ty = tid >> 4;
    int bm0 = blockIdx.y * 128, bn0 = blockIdx.x * 128;
    int ar  = tid >> 2, ac4 = tid & 3;
    int bkr = tid >> 5, bc4 = tid & 31;

    float acc[8][8];
#pragma unroll
    for (int i = 0; i < 8; i++)
#pragma unroll
        for (int j = 0; j < 8; j++) acc[i][j] = 0.f;

    for (int k0 = 0; k0 < K; k0 += 16) {
#pragma unroll
        for (int it = 0; it < 2; it++) {
            int r = ar + it * 64;
            float4 a = *(const float4*)(A + (size_t)(bm0 + r) * K + k0 + ac4 * 4);
            As[ac4*4+0][r] = a.x; As[ac4*4+1][r] = a.y;
            As[ac4*4+2][r] = a.z; As[ac4*4+3][r] = a.w;
        }
#pragma unroll
        for (int it = 0; it < 2; it++) {
            int kr = bkr + it * 8;
            *(float4*)&Bs[kr][bc4*4] =
                *(const float4*)(B + (size_t)(k0 + kr) * ldb + bn0 + bc4 * 4);
        }
        __syncthreads();
#pragma unroll
        for (int k = 0; k < 16; k++) {
            float a0[8], b0[8];
            *(float4*)&a0[0] = *(float4*)&As[k][ty*4];
            *(float4*)&a0[4] = *(float4*)&As[k][ty*4 + 64];
            *(float4*)&b0[0] = *(float4*)&Bs[k][tx*4];
            *(float4*)&b0[4] = *(float4*)&Bs[k][tx*4 + 64];
#pragma unroll
            for (int i = 0; i < 8; i++)
#pragma unroll
                for (int j = 0; j < 8; j++)
                    acc[i][j] = fmaf(a0[i], b0[j], acc[i][j]);
        }
        __syncthreads();
    }

    if (PU == nullptr) {
#pragma unroll
        for (int i = 0; i < 8; i++) {
            int row = bm0 + ty*4 + (i < 4 ? i : 64 + i - 4);
#pragma unroll
            for (int jb = 0; jb < 2; jb++) {
                int col = bn0 + tx*4 + jb*64;
                float4 v;
                v.x = acc[i][jb*4+0]; v.y = acc[i][jb*4+1];
                v.z = acc[i][jb*4+2]; v.w = acc[i][jb*4+3];
                if (bias) {
                    float4 bv = *(const float4*)(bias + col);
                    v.x += bv.x; v.y += bv.y; v.z += bv.z; v.w += bv.w;
                }
                if (relu) {
                    v.x = fmaxf(v.x, 0.f); v.y = fmaxf(v.y, 0.f);
                    v.z = fmaxf(v.z, 0.f); v.w = fmaxf(v.w, 0.f);
                }
                *(float4*)(C + (size_t)row * ldb + col) = v;
            }
        }
    } else {
#pragma unroll
        for (int i = 0; i < 8; i++) {
            int row = bm0 + ty*4 + (i < 4 ? i : 64 + i - 4);
            int u = row & (UU-1);
            const float* pur = PU + (size_t)u * NP;
            float* crow = C + (size_t)row * NN;
#pragma unroll
            for (int jb = 0; jb < 2; jb++) {
                int col = bn0 + tx*4 + jb*64;
                if (col + 3 < NN) {
                    float2 v0, v1;
                    v0.x = acc[i][jb*4+0] + pur[col+0];
                    v0.y = acc[i][jb*4+1] + pur[col+1];
                    v1.x = acc[i][jb*4+2] + pur[col+2];
                    v1.y = acc[i][jb*4+3] + pur[col+3];
                    *(float2*)(crow + col)     = v0;   // row*20002 is 8B aligned
                    *(float2*)(crow + col + 2) = v1;
                } else {
#pragma unroll
                    for (int j = 0; j < 4; j++)
                        if (col + j < NN) crow[col+j] = acc[i][jb*4+j] + pur[col+j];
                }
            }
        }
    }
}

// ---------------- host launcher ----------------
extern "C" void kernel_launch(void* const* d_in, const int* in_sizes, int n_in,
                              void* d_out, int out_size)
{
    const int*   x      = (const int*)  d_in[0];
    // d_in[1] = x_adj (unused by reference)
    const int*   indexs = (const int*)  d_in[2];
    const float* s      = (const float*)d_in[3];
    const int*   au     = (const int*)  d_in[4];
    const int*   grows  = (const int*)  d_in[5];
    const int*   gcols  = (const int*)  d_in[6];
    const float* gvals  = (const float*)d_in[7];
    const int*   irows  = (const int*)  d_in[8];
    const int*   icols  = (const int*)  d_in[9];
    const float* ivals  = (const float*)d_in[10];
    const float* enc    = (const float*)d_in[11];
    const float* ut     = (const float*)d_in[12];
    const float* Wq     = (const float*)d_in[13];
    const float* Wk     = (const float*)d_in[14];
    const float* Wv     = (const float*)d_in[15];
    const float* Wo     = (const float*)d_in[16];
    const float* ln1g   = (const float*)d_in[17];
    const float* ln1b   = (const float*)d_in[18];
    const float* ln2g   = (const float*)d_in[19];
    const float* ln2b   = (const float*)d_in[20];
    const float* w1     = (const float*)d_in[21];
    const float* b1     = (const float*)d_in[22];
    const float* w2     = (const float*)d_in[23];
    const float* b2     = (const float*)d_in[24];
    const float* fcw    = (const float*)d_in[25];
    const float* fcb    = (const float*)d_in[26];
    float* out = (float*)d_out;

    // symbol addresses (host-side queries; graph-capture safe)
    void *p_xemb, *p_q, *p_k, *p_v, *p_av, *p_t1, *p_h1, *p_f1, *p_t2,
         *p_Ag, *p_Bp, *p_fcbp, *p_PU, *p_pug;
    cudaGetSymbolAddress(&p_xemb, g_xemb);
    cudaGetSymbolAddress(&p_q,    g_q);
    cudaGetSymbolAddress(&p_k,    g_k);
    cudaGetSymbolAddress(&p_v,    g_v);
    cudaGetSymbolAddress(&p_av,   g_av);
    cudaGetSymbolAddress(&p_t1,   g_t1);
    cudaGetSymbolAddress(&p_h1,   g_h1);
    cudaGetSymbolAddress(&p_f1,   g_f1);
    cudaGetSymbolAddress(&p_t2,   g_t2);
    cudaGetSymbolAddress(&p_Ag,   g_Ag);
    cudaGetSymbolAddress(&p_Bp,   g_Bp);
    cudaGetSymbolAddress(&p_fcbp, g_fcbp);
    cudaGetSymbolAddress(&p_PU,   g_PU);
    cudaGetSymbolAddress(&p_pug,  g_pug);
    float* xemb = (float*)p_xemb;  float* q  = (float*)p_q;
    float* kk   = (float*)p_k;     float* v  = (float*)p_v;
    float* av   = (float*)p_av;    float* t1 = (float*)p_t1;
    float* h1   = (float*)p_h1;    float* f1 = (float*)p_f1;
    float* t2   = (float*)p_t2;    float* Ag = (float*)p_Ag;
    float* Bp   = (float*)p_Bp;    float* fcbp = (float*)p_fcbp;
    float* PU   = (float*)p_PU;    float* pug  = (float*)p_pug;

    // also need h2 / ln params path through globals
    void *p_h2; cudaGetSymbolAddress(&p_h2, g_h2); float* h2 = (float*)p_h2;

    // 1) zero accumulators + masks, set masks, repack fc_w
    k_zero<<<8192, 256>>>();
    k_setmask<<<(MM + 255) / 256, 256>>>(x, au);
    k_repack<<<8192, 256>>>(fcw, fcb);

    // 2) masked segment sums
    k_scatter<<<(NNZG + 7) / 8, 256>>>(grows, gcols, gvals, enc, NNZG, 0);
    k_scatter<<<(NNZI + 7) / 8, 256>>>(irows, icols, ivals, enc, NNZI, 1);

    // 3) gathers + x_emb + sim
    k_upref<<<UU, HH>>>(au);
    k_pug<<<UU, HH>>>(au, ut);
    k_xemb<<<MM, HH>>>(x, enc);

    // 4) transformer
    dim3 blk(256);
    sgemm_k<<<dim3(2, 50), blk>>>(xemb, Wq, q,  HH, HH, nullptr, 0, nullptr);
    sgemm_k<<<dim3(2, 50), blk>>>(xemb, Wk, kk, HH, HH, nullptr, 0, nullptr);
    sgemm_k<<<dim3(2, 50), blk>>>(xemb, Wv, v,  HH, HH, nullptr, 0, nullptr);
    k_attn<<<UU, 256>>>();
    sgemm_k<<<dim3(2, 50), blk>>>(av, Wo, t1, HH, HH, nullptr, 0, nullptr);
    k_ln<<<MM, HH>>>(xemb, t1, h1, ln1g, ln1b);
    sgemm_k<<<dim3(8, 50), blk>>>(h1, w1, f1, HH, 4*HH, b1, 1, nullptr);
    sgemm_k<<<dim3(2, 50), blk>>>(f1, w2, t2, 4*HH, HH, b2, 0, nullptr);
    k_ln<<<MM, HH>>>(h1, t2, h2, ln2g, ln2b);

    // 5) spatial weighting + gather rows
    k_spatial<<<MM, HH>>>(s);
    k_buildA<<<MM, HH>>>(indexs);

    // 6) PU = p_u @ fc_w[256:] + fc_b   (128 x 20096, K=256)
    sgemm_k<<<dim3(NP / 128, 1), blk>>>(pug, Bp + (size_t)256 * NP, PU,
                                        HH, NP, fcbp, 0, nullptr);

    // 7) final: out = gathered_out_w @ fc_w[:256] + PU  (6400 x 20002, K=256)
    sgemm_k<<<dim3(NP / 128, MM / 128), blk>>>(Ag, Bp, out, HH, NP,
                                               nullptr, 0, PU);
    (void)in_sizes; (void)n_in; (void)out_size;
}

// round 2
// speedup vs baseline: 1.4196x; 1.4196x over previous
#include <cuda_runtime.h>
#include <cuda_bf16.h>
#include <cstdint>
#include <cstddef>

// ---------------- problem constants ----------------
#define SS 50
#define UU 128
#define NN 20002
#define HH 256
#define UCNT 5000
#define NNZG 200000
#define NNZI 100000
#define MM (SS*UU)          // 6400
#define NP 20096            // 20002 padded to multiple of 128
#define KK3 768             // 3*256 split-bf16 K

// ---------------- device scratch ----------------
__device__ float g_ew   [(size_t)NN*HH];
__device__ float g_ewu  [(size_t)UCNT*HH];
__device__ float g_upref[(size_t)UU*HH];
__device__ float g_pug  [(size_t)UU*HH];
__device__ float g_xemb [(size_t)MM*HH];
__device__ float g_sim  [MM];
__device__ float g_q    [(size_t)MM*HH];
__device__ float g_k    [(size_t)MM*HH];
__device__ float g_v    [(size_t)MM*HH];
__device__ float g_av   [(size_t)MM*HH];
__device__ float g_t1   [(size_t)MM*HH];
__device__ float g_h1   [(size_t)MM*HH];
__device__ float g_f1   [(size_t)MM*4*HH];
__device__ float g_t2   [(size_t)MM*HH];
__device__ float g_h2   [(size_t)MM*HH];
__device__ float g_outw [(size_t)MM*HH];
__device__ float g_Ag   [(size_t)MM*HH];
__device__ float g_Bp   [(size_t)256*NP];    // fc_w rows 256..511, padded
__device__ float g_fcbp [NP];
__device__ float g_PU   [(size_t)UU*NP];
__device__ __nv_bfloat16 g_Ab[(size_t)MM*KK3];    // [Ahi|Alo|Ahi]
__device__ __nv_bfloat16 g_Bb[(size_t)KK3*NP];    // [Bhi;Bhi;Blo]
__device__ unsigned char g_need [NN];
__device__ unsigned char g_umask[UCNT];

// ---------------- zero accumulators + masks ----------------
__global__ void k_zero()
{
    int i = blockIdx.x * blockDim.x + threadIdx.x;
    int stride = gridDim.x * blockDim.x;
    const int tot = NN*HH + UCNT*HH;
    for (int j = i; j < tot; j += stride) {
        if (j < NN*HH) g_ew[j] = 0.f; else g_ewu[j - NN*HH] = 0.f;
    }
    if (i < NN)   g_need[i]  = 0;
    if (i < UCNT) g_umask[i] = 0;
}

__global__ void k_setmask(const int* __restrict__ x, const int* __restrict__ au)
{
    int i = blockIdx.x * blockDim.x + threadIdx.x;
    if (i < MM) { int xv = x[i]; if (xv < NN-2) g_need[xv] = 1; }
    if (i < UU) g_umask[au[i]] = 1;
}

// ---------------- repack fc_w rows 256..511 for the PU GEMM ----------------
__global__ void k_repack(const float* __restrict__ fcw, const float* __restrict__ fcb)
{
    int i = blockIdx.x * blockDim.x + threadIdx.x;
    int stride = gridDim.x * blockDim.x;
    const int tot = 256 * NP;
    for (int j = i; j < tot; j += stride) {
        int k = j / NP, n = j - k * NP;
        g_Bp[j] = (n < NN) ? fcw[(size_t)(256 + k) * NN + n] : 0.f;
    }
    if (i < NP) g_fcbp[i] = (i < NN) ? fcb[i] : 0.f;
}

// ---------------- split-bf16 conversion of fc_w rows 0..255 ----------------
__global__ void k_convB(const float* __restrict__ fcw)
{
    int i = blockIdx.x * blockDim.x + threadIdx.x;
    int stride = gridDim.x * blockDim.x;
    const int tot = 256 * NP;
    for (int j = i; j < tot; j += stride) {
        int k = j / NP, n = j - k * NP;
        float x = (n < NN) ? fcw[(size_t)k * NN + n] : 0.f;
        __nv_bfloat16 hi = __float2bfloat16(x);
        __nv_bfloat16 lo = __float2bfloat16(x - __bfloat162float(hi));
        g_Bb[(size_t)k * NP + n]         = hi;
        g_Bb[(size_t)(256 + k) * NP + n] = hi;
        g_Bb[(size_t)(512 + k) * NP + n] = lo;
    }
}

// ---------------- split-bf16 conversion of gathered A ----------------
__global__ void k_convA()
{
    int m = blockIdx.x, h = threadIdx.x;
    float x = g_Ag[(size_t)m * HH + h];
    __nv_bfloat16 hi = __float2bfloat16(x);
    __nv_bfloat16 lo = __float2bfloat16(x - __bfloat162float(hi));
    g_Ab[(size_t)m * KK3 + h]       = hi;
    g_Ab[(size_t)m * KK3 + 256 + h] = lo;
    g_Ab[(size_t)m * KK3 + 512 + h] = hi;
}

// ---------------- masked sparse scatter (warp per edge) ----------------
__global__ void k_scatter(const int* __restrict__ rows, const int* __restrict__ cols,
                          const float* __restrict__ vals, const float* __restrict__ enc,
                          int nnz, int which)
{
    int e = (blockIdx.x * blockDim.x + threadIdx.x) >> 5;
    if (e >= nnz) return;
    int lane = threadIdx.x & 31;
    int r = rows[e];
    const unsigned char* mask = which ? g_umask : g_need;
    if (!mask[r]) return;
    float v = vals[e];
    float* dst = (which ? g_ewu : g_ew) + (size_t)r * HH;
    const float4* src = (const float4*)(enc + (size_t)cols[e] * HH);
#pragma unroll
    for (int j = 0; j < 2; j++) {
        float4 t = src[lane + 32*j];
        int h = (lane + 32*j) * 4;
        atomicAdd(dst + h + 0, v * t.x);
        atomicAdd(dst + h + 1, v * t.y);
        atomicAdd(dst + h + 2, v * t.z);
        atomicAdd(dst + h + 3, v * t.w);
    }
}

// ---------------- small gathers ----------------
__global__ void k_upref(const int* __restrict__ au)
{
    int u = blockIdx.x, h = threadIdx.x;
    g_upref[(size_t)u*HH + h] = g_ewu[(size_t)au[u]*HH + h];
}
__global__ void k_pug(const int* __restrict__ au, const float* __restrict__ ut)
{
    int u = blockIdx.x, h = threadIdx.x;
    g_pug[(size_t)u*HH + h] = ut[(size_t)au[u]*HH + h];
}

// ---------------- x_emb gather + sim ----------------
__global__ void k_xemb(const int* __restrict__ x, const float* __restrict__ enc)
{
    int m = blockIdx.x, h = threadIdx.x;
    int u = m & (UU-1);
    int xv = x[m];
    float val = (xv >= NN-2) ? enc[(size_t)xv*HH + h] : g_ew[(size_t)xv*HH + h];
    g_xemb[(size_t)m*HH + h] = val;
    float d = g_upref[(size_t)u*HH + h] - val;
    __shared__ float red[HH];
    red[h] = d * d;
    __syncthreads();
    for (int s2 = 128; s2 > 0; s2 >>= 1) {
        if (h < s2) red[h] += red[h + s2];
        __syncthreads();
    }
    if (h == 0) g_sim[m] = expf(-sqrtf(red[0]));
}

// ---------------- causal attention (block per u) ----------------
__global__ void k_attn()
{
    int u = blockIdx.x;
    int warp = threadIdx.x >> 5, lane = threadIdx.x & 31;
    __shared__ float sp[8][56];
    for (int i = warp; i < SS; i += 8) {
        const float* qi = g_q + ((size_t)i*UU + u) * HH;
        float mx = -1e30f;
        for (int j = 0; j <= i; j++) {
            const float* kj = g_k + ((size_t)j*UU + u) * HH;
            float d = 0.f;
#pragma unroll
            for (int t = 0; t < 8; t++) d += qi[lane + 32*t] * kj[lane + 32*t];
            for (int o = 16; o; o >>= 1) d += __shfl_xor_sync(0xffffffffu, d, o);
            d *= 0.0625f;
            sp[warp][j] = d;
            mx = fmaxf(mx, d);
        }
        __syncwarp();
        float ssum = 0.f;
        for (int j = lane; j <= i; j += 32) {
            float e = expf(sp[warp][j] - mx);
            sp[warp][j] = e;
            ssum += e;
        }
        __syncwarp();
        for (int o = 16; o; o >>= 1) ssum += __shfl_xor_sync(0xffffffffu, ssum, o);
        float inv = 1.f / ssum;
        float acc[8];
#pragma unroll
        for (int t = 0; t < 8; t++) acc[t] = 0.f;
        for (int j = 0; j <= i; j++) {
            float p = sp[warp][j] * inv;
            const float* vj = g_v + ((size_t)j*UU + u) * HH;
#pragma unroll
            for (int t = 0; t < 8; t++) acc[t] = fmaf(p, vj[lane + 32*t], acc[t]);
        }
        float* o = g_av + ((size_t)i*UU + u) * HH;
#pragma unroll
        for (int t = 0; t < 8; t++) o[lane + 32*t] = acc[t];
        __syncwarp();
    }
}

// ---------------- residual + LayerNorm ----------------
__global__ void k_ln(const float* __restrict__ Xres, const float* __restrict__ Y,
                     float* __restrict__ Out, const float* __restrict__ g,
                     const float* __restrict__ b)
{
    int m = blockIdx.x, h = threadIdx.x;
    float v = Xres[(size_t)m*HH + h] + Y[(size_t)m*HH + h];
    __shared__ float red[HH];
    red[h] = v;
    __syncthreads();
    for (int s2 = 128; s2 > 0; s2 >>= 1) { if (h < s2) red[h] += red[h + s2]; __syncthreads(); }
    float mu = red[0] * (1.f / HH);
    __syncthreads();
    float d = v - mu;
    red[h] = d * d;
    __syncthreads();
    for (int s2 = 128; s2 > 0; s2 >>= 1) { if (h < s2) red[h] += red[h + s2]; __syncthreads(); }
    float var = red[0] * (1.f / HH);
    Out[(size_t)m*HH + h] = d * rsqrtf(var + 1e-5f) * g[h] + b[h];
}

// ---------------- spatial weighting ----------------
__global__ void k_spatial(const float* __restrict__ s)
{
    int m = blockIdx.x;
    int i = m >> 7, u = m & (UU-1);
    int h = threadIdx.x;
    __shared__ float w[64];
    __shared__ float sumw;
    float sx = s[((size_t)i*UU + u)*2 + 0];
    float sy = s[((size_t)i*UU + u)*2 + 1];
    if (h < SS) {
        float wj = 0.f;
        if (h <= i) {
            float dx = sx - s[((size_t)h*UU + u)*2 + 0];
            float dy = sy - s[((size_t)h*UU + u)*2 + 1];
            wj = (expf(-sqrtf(dx*dx + dy*dy)) + 1e-10f) * g_sim[(size_t)h*UU + u];
        }
        w[h] = wj;
    }
    __syncthreads();
    if (h == 0) {
        float t = 0.f;
        for (int j = 0; j < SS; j++) t += w[j];
        sumw = t;
    }
    __syncthreads();
    float acc = 0.f;
    for (int j = 0; j <= i; j++)
        acc = fmaf(w[j], g_h2[((size_t)j*UU + u)*HH + h], acc);
    g_outw[(size_t)m*HH + h] = acc / sumw;
}

// ---------------- gather out_w rows by indexs ----------------
__global__ void k_buildA(const int* __restrict__ indexs)
{
    int m = blockIdx.x, h = threadIdx.x;
    int u = m & (UU-1);
    int j = indexs[m];
    g_Ag[(size_t)m*HH + h] = g_outw[((size_t)j*UU + u)*HH + h];
}

// ---------------- fp32 SGEMM (kept for transformer + PU) ----------------
__global__ void __launch_bounds__(256, 2)
sgemm_k(const float* __restrict__ A, const float* __restrict__ B,
        float* __restrict__ C, int K, int ldb,
        const float* __restrict__ bias, int relu)
{
    __shared__ float As[16][132];
    __shared__ float Bs[16][128];
    int tid = threadIdx.x;
    int tx = tid & 15, ty = tid >> 4;
    int bm0 = blockIdx.y * 128, bn0 = blockIdx.x * 128;
    int ar  = tid >> 2, ac4 = tid & 3;
    int bkr = tid >> 5, bc4 = tid & 31;

    float acc[8][8];
#pragma unroll
    for (int i = 0; i < 8; i++)
#pragma unroll
        for (int j = 0; j < 8; j++) acc[i][j] = 0.f;

    for (int k0 = 0; k0 < K; k0 += 16) {
#pragma unroll
        for (int it = 0; it < 2; it++) {
            int r = ar + it * 64;
            float4 a = *(const float4*)(A + (size_t)(bm0 + r) * K + k0 + ac4 * 4);
            As[ac4*4+0][r] = a.x; As[ac4*4+1][r] = a.y;
            As[ac4*4+2][r] = a.z; As[ac4*4+3][r] = a.w;
        }
#pragma unroll
        for (int it = 0; it < 2; it++) {
            int kr = bkr + it * 8;
            *(float4*)&Bs[kr][bc4*4] =
                *(const float4*)(B + (size_t)(k0 + kr) * ldb + bn0 + bc4 * 4);
        }
        __syncthreads();
#pragma unroll
        for (int k = 0; k < 16; k++) {
            float a0[8], b0[8];
            *(float4*)&a0[0] = *(float4*)&As[k][ty*4];
            *(float4*)&a0[4] = *(float4*)&As[k][ty*4 + 64];
            *(float4*)&b0[0] = *(float4*)&Bs[k][tx*4];
            *(float4*)&b0[4] = *(float4*)&Bs[k][tx*4 + 64];
#pragma unroll
            for (int i = 0; i < 8; i++)
#pragma unroll
                for (int j = 0; j < 8; j++)
                    acc[i][j] = fmaf(a0[i], b0[j], acc[i][j]);
        }
        __syncthreads();
    }

#pragma unroll
    for (int i = 0; i < 8; i++) {
        int row = bm0 + ty*4 + (i < 4 ? i : 64 + i - 4);
#pragma unroll
        for (int jb = 0; jb < 2; jb++) {
            int col = bn0 + tx*4 + jb*64;
            float4 v;
            v.x = acc[i][jb*4+0]; v.y = acc[i][jb*4+1];
            v.z = acc[i][jb*4+2]; v.w = acc[i][jb*4+3];
            if (bias) {
                float4 bv = *(const float4*)(bias + col);
                v.x += bv.x; v.y += bv.y; v.z += bv.z; v.w += bv.w;
            }
            if (relu) {
                v.x = fmaxf(v.x, 0.f); v.y = fmaxf(v.y, 0.f);
                v.z = fmaxf(v.z, 0.f); v.w = fmaxf(v.w, 0.f);
            }
            *(float4*)(C + (size_t)row * ldb + col) = v;
        }
    }
}

// ---------------- tensor-core bf16 GEMM for the final FC ----------------
// C[6400 x 20002] = Ab[6400 x 768] @ Bb[768 x 20096] + PU[row&127][col]
#define AS_STRIDE 40     // bf16 elems per smem A row (32 data + 8 pad)
#define BS_STRIDE 136    // bf16 elems per smem B row (128 data + 8 pad)
#define A_BUF (128*AS_STRIDE)
#define B_BUF (32*BS_STRIDE)
#define KTILES (KK3/32)  // 24

__device__ __forceinline__ void cp16(uint32_t saddr, const void* gaddr)
{
    asm volatile("cp.async.cg.shared.global [%0], [%1], 16;\n"
                 :: "r"(saddr), "l"(gaddr));
}
__device__ __forceinline__ void cp_commit()
{
    asm volatile("cp.async.commit_group;\n");
}

__global__ void __launch_bounds__(256)
gemm_tc(const __nv_bfloat16* __restrict__ A, const __nv_bfloat16* __restrict__ B,
        float* __restrict__ C, const float* __restrict__ PU)
{
    __shared__ __nv_bfloat16 As[2][A_BUF];
    __shared__ __nv_bfloat16 Bs[2][B_BUF];

    int tid  = threadIdx.x;
    int warp = tid >> 5, lane = tid & 31;
    int warpM = warp >> 1, warpN = warp & 1;       // 4x2 warp grid
    int bm0 = blockIdx.y * 128, bn0 = blockIdx.x * 128;

    uint32_t as0 = (uint32_t)__cvta_generic_to_shared(&As[0][0]);
    uint32_t bs0 = (uint32_t)__cvta_generic_to_shared(&Bs[0][0]);

    // global->smem load coords
    int t4  = tid & 3,  rA = tid >> 2;    // A: rows rA, rA+64; col chunk t4*8
    int t16 = tid & 15, rB = tid >> 4;    // B: rows rB, rB+16; col chunk t16*8

    // ldmatrix per-lane offsets (bytes)
    uint32_t aoff = ((uint32_t)((warpM*32 + (lane & 15)) * AS_STRIDE
                    + ((lane >> 4) << 3))) * 2;
    uint32_t boff = ((uint32_t)((lane & 15) * BS_STRIDE
                    + warpN*64 + ((lane >> 4) << 3))) * 2;

    float acc[2][8][4];
#pragma unroll
    for (int mi = 0; mi < 2; mi++)
#pragma unroll
        for (int n8 = 0; n8 < 8; n8++)
#pragma unroll
            for (int r = 0; r < 4; r++) acc[mi][n8][r] = 0.f;

    auto issue = [&](int t, int buf) {
        int k0 = t * 32;
        uint32_t asb = as0 + buf * (A_BUF * 2);
        uint32_t bsb = bs0 + buf * (B_BUF * 2);
        cp16(asb + (rA*AS_STRIDE + t4*8)*2,
             A + (size_t)(bm0 + rA) * KK3 + k0 + t4*8);
        cp16(asb + ((rA+64)*AS_STRIDE + t4*8)*2,
             A + (size_t)(bm0 + rA + 64) * KK3 + k0 + t4*8);
        cp16(bsb + (rB*BS_STRIDE + t16*8)*2,
             B + (size_t)(k0 + rB) * NP + bn0 + t16*8);
        cp16(bsb + ((rB+16)*BS_STRIDE + t16*8)*2,
             B + (size_t)(k0 + rB + 16) * NP + bn0 + t16*8);
        cp_commit();
    };

    issue(0, 0);

    for (int t = 0; t < KTILES; t++) {
        if (t + 1 < KTILES) {
            issue(t + 1, (t + 1) & 1);
            asm volatile("cp.async.wait_group 1;\n");
        } else {
            asm volatile("cp.async.wait_group 0;\n");
        }
        __syncthreads();

        int buf = t & 1;
        uint32_t asb = as0 + buf * (A_BUF * 2);
        uint32_t bsb = bs0 + buf * (B_BUF * 2);
#pragma unroll
        for (int s = 0; s < 2; s++) {
            uint32_t a[2][4];
#pragma unroll
            for (int mi = 0; mi < 2; mi++) {
                uint32_t addr = asb + aoff + (uint32_t)(mi*16*AS_STRIDE + s*16)*2;
                asm volatile("ldmatrix.sync.aligned.m8n8.x4.shared.b16 "
                             "{%0,%1,%2,%3}, [%4];"
                             : "=r"(a[mi][0]), "=r"(a[mi][1]),
                               "=r"(a[mi][2]), "=r"(a[mi][3])
                             : "r"(addr));
            }
            uint32_t bf[4][4];
#pragma unroll
            for (int nj = 0; nj < 4; nj++) {
                uint32_t addr = bsb + boff + (uint32_t)(s*16*BS_STRIDE + nj*16)*2;
                asm volatile("ldmatrix.sync.aligned.m8n8.x4.trans.shared.b16 "
                             "{%0,%1,%2,%3}, [%4];"
                             : "=r"(bf[nj][0]), "=r"(bf[nj][1]),
                               "=r"(bf[nj][2]), "=r"(bf[nj][3])
                             : "r"(addr));
            }
#pragma unroll
            for (int mi = 0; mi < 2; mi++)
#pragma unroll
                for (int n8 = 0; n8 < 8; n8++) {
                    uint32_t b0 = bf[n8 >> 1][(n8 & 1) * 2 + 0];
                    uint32_t b1 = bf[n8 >> 1][(n8 & 1) * 2 + 1];
                    asm volatile(
                        "mma.sync.aligned.m16n8k16.row.col.f32.bf16.bf16.f32 "
                        "{%0,%1,%2,%3}, {%4,%5,%6,%7}, {%8,%9}, {%0,%1,%2,%3};"
                        : "+f"(acc[mi][n8][0]), "+f"(acc[mi][n8][1]),
                          "+f"(acc[mi][n8][2]), "+f"(acc[mi][n8][3])
                        : "r"(a[mi][0]), "r"(a[mi][1]),
                          "r"(a[mi][2]), "r"(a[mi][3]),
                          "r"(b0), "r"(b1));
                }
        }
        __syncthreads();
    }

    // epilogue: add PU, bounded store to 20002-wide C
#pragma unroll
    for (int mi = 0; mi < 2; mi++) {
        int r0 = bm0 + warpM*32 + mi*16 + (lane >> 2);
        int r1 = r0 + 8;
#pragma unroll
        for (int n8 = 0; n8 < 8; n8++) {
            int col = bn0 + warpN*64 + n8*8 + (lane & 3)*2;
            if (col < NN) {     // col even, NN even -> pair fully in-bounds
                const float* pu0 = PU + (size_t)(r0 & (UU-1)) * NP + col;
                const float* pu1 = PU + (size_t)(r1 & (UU-1)) * NP + col;
                float2 v0, v1;
                v0.x = acc[mi][n8][0] + pu0[0];
                v0.y = acc[mi][n8][1] + pu0[1];
                v1.x = acc[mi][n8][2] + pu1[0];
                v1.y = acc[mi][n8][3] + pu1[1];
                *(float2*)(C + (size_t)r0 * NN + col) = v0;
                *(float2*)(C + (size_t)r1 * NN + col) = v1;
            }
        }
    }
}

// ---------------- host launcher ----------------
extern "C" void kernel_launch(void* const* d_in, const int* in_sizes, int n_in,
                              void* d_out, int out_size)
{
    const int*   x      = (const int*)  d_in[0];
    const int*   indexs = (const int*)  d_in[2];
    const float* s      = (const float*)d_in[3];
    const int*   au     = (const int*)  d_in[4];
    const int*   grows  = (const int*)  d_in[5];
    const int*   gcols  = (const int*)  d_in[6];
    const float* gvals  = (const float*)d_in[7];
    const int*   irows  = (const int*)  d_in[8];
    const int*   icols  = (const int*)  d_in[9];
    const float* ivals  = (const float*)d_in[10];
    const float* enc    = (const float*)d_in[11];
    const float* ut     = (const float*)d_in[12];
    const float* Wq     = (const float*)d_in[13];
    const float* Wk     = (const float*)d_in[14];
    const float* Wv     = (const float*)d_in[15];
    const float* Wo     = (const float*)d_in[16];
    const float* ln1g   = (const float*)d_in[17];
    const float* ln1b   = (const float*)d_in[18];
    const float* ln2g   = (const float*)d_in[19];
    const float* ln2b   = (const float*)d_in[20];
    const float* w1     = (const float*)d_in[21];
    const float* b1     = (const float*)d_in[22];
    const float* w2     = (const float*)d_in[23];
    const float* b2     = (const float*)d_in[24];
    const float* fcw    = (const float*)d_in[25];
    const float* fcb    = (const float*)d_in[26];
    float* out = (float*)d_out;

    void *p_xemb, *p_q, *p_k, *p_v, *p_av, *p_t1, *p_h1, *p_f1, *p_t2,
         *p_Bp, *p_fcbp, *p_PU, *p_pug, *p_h2, *p_Ab, *p_Bb;
    cudaGetSymbolAddress(&p_xemb, g_xemb);
    cudaGetSymbolAddress(&p_q,    g_q);
    cudaGetSymbolAddress(&p_k,    g_k);
    cudaGetSymbolAddress(&p_v,    g_v);
    cudaGetSymbolAddress(&p_av,   g_av);
    cudaGetSymbolAddress(&p_t1,   g_t1);
    cudaGetSymbolAddress(&p_h1,   g_h1);
    cudaGetSymbolAddress(&p_f1,   g_f1);
    cudaGetSymbolAddress(&p_t2,   g_t2);
    cudaGetSymbolAddress(&p_Bp,   g_Bp);
    cudaGetSymbolAddress(&p_fcbp, g_fcbp);
    cudaGetSymbolAddress(&p_PU,   g_PU);
    cudaGetSymbolAddress(&p_pug,  g_pug);
    cudaGetSymbolAddress(&p_h2,   g_h2);
    cudaGetSymbolAddress(&p_Ab,   g_Ab);
    cudaGetSymbolAddress(&p_Bb,   g_Bb);
    float* xemb = (float*)p_xemb;  float* q  = (float*)p_q;
    float* kk   = (float*)p_k;     float* v  = (float*)p_v;
    float* av   = (float*)p_av;    float* t1 = (float*)p_t1;
    float* h1   = (float*)p_h1;    float* f1 = (float*)p_f1;
    float* t2   = (float*)p_t2;    float* h2 = (float*)p_h2;
    float* Bp   = (float*)p_Bp;    float* fcbp = (float*)p_fcbp;
    float* PU   = (float*)p_PU;    float* pug  = (float*)p_pug;
    __nv_bfloat16* Ab = (__nv_bfloat16*)p_Ab;
    __nv_bfloat16* Bb = (__nv_bfloat16*)p_Bb;

    // 1) init + repack + split-bf16 B conversion (independent of data path)
    k_zero<<<8192, 256>>>();
    k_setmask<<<(MM + 255) / 256, 256>>>(x, au);
    k_repack<<<4096, 256>>>(fcw, fcb);
    k_convB<<<4096, 256>>>(fcw);

    // 2) masked segment sums
    k_scatter<<<(NNZG + 7) / 8, 256>>>(grows, gcols, gvals, enc, NNZG, 0);
    k_scatter<<<(NNZI + 7) / 8, 256>>>(irows, icols, ivals, enc, NNZI, 1);

    // 3) gathers + x_emb + sim
    k_upref<<<UU, HH>>>(au);
    k_pug<<<UU, HH>>>(au, ut);
    k_xemb<<<MM, HH>>>(x, enc);

    // 4) transformer
    dim3 blk(256);
    sgemm_k<<<dim3(2, 50), blk>>>(xemb, Wq, q,  HH, HH, nullptr, 0);
    sgemm_k<<<dim3(2, 50), blk>>>(xemb, Wk, kk, HH, HH, nullptr, 0);
    sgemm_k<<<dim3(2, 50), blk>>>(xemb, Wv, v,  HH, HH, nullptr, 0);
    k_attn<<<UU, 256>>>();
    sgemm_k<<<dim3(2, 50), blk>>>(av, Wo, t1, HH, HH, nullptr, 0);
    k_ln<<<MM, HH>>>(xemb, t1, h1, ln1g, ln1b);
    sgemm_k<<<dim3(8, 50), blk>>>(h1, w1, f1, HH, 4*HH, b1, 1);
    sgemm_k<<<dim3(2, 50), blk>>>(f1, w2, t2, 4*HH, HH, b2, 0);
    k_ln<<<MM, HH>>>(h1, t2, h2, ln2g, ln2b);

    // 5) spatial weighting + row gather + A conversion
    k_spatial<<<MM, HH>>>(s);
    k_buildA<<<MM, HH>>>(indexs);
    k_convA<<<MM, HH>>>();

    // 6) PU = p_u @ fc_w[256:] + fc_b   (128 x 20096, K=256, fp32)
    sgemm_k<<<dim3(NP / 128, 1), blk>>>(pug, Bp, PU, HH, NP, fcbp, 0);

    // 7) final: out = Ab @ Bb + PU      (tensor cores, split-bf16)
    gemm_tc<<<dim3(NP / 128, MM / 128), blk>>>(Ab, Bb, out, PU);

    (void)in_sizes; (void)n_in; (void)out_size;
}